// round 4
// baseline (speedup 1.0000x reference)
#include <cuda_runtime.h>
#include <cstdint>

#define N_NODES 50000
#define N_REL   16
#define N_BASIS 8
#define D_IN    64
#define D_HID   64
#define N_CLASS 16
#define N_EDGES 800000

// ---------------- device scratch (static, allowed) ----------------
__device__ __align__(16) float g_W1[N_REL * D_IN * D_HID];      // 256 KB
__device__ __align__(16) float g_W2[N_REL * D_HID * N_CLASS];   // 64 KB
__device__ __align__(16) float g_T1[N_REL * N_NODES * D_HID];   // 204.8 MB
__device__ __align__(16) float g_T2[N_REL * N_NODES * N_CLASS]; // 51.2 MB
__device__ __align__(16) float g_h [N_NODES * D_HID];           // 12.8 MB
__device__ __align__(16) int   g_cnt[N_REL * N_NODES];          // 3.2 MB

// ---------------- tiny setup kernels ----------------
__global__ void k_weights(const float* __restrict__ bases1, const float* __restrict__ coeffs1,
                          const float* __restrict__ bases2, const float* __restrict__ coeffs2)
{
    int blk = blockIdx.x;
    int r = blk & 15;
    if (blk < 16) {
        for (int i = threadIdx.x; i < D_IN * D_HID; i += blockDim.x) {
            float s = 0.f;
            #pragma unroll
            for (int b = 0; b < N_BASIS; b++)
                s += coeffs1[r * N_BASIS + b] * bases1[b * D_IN * D_HID + i];
            g_W1[r * D_IN * D_HID + i] = s;
        }
    } else {
        for (int i = threadIdx.x; i < D_HID * N_CLASS; i += blockDim.x) {
            float s = 0.f;
            #pragma unroll
            for (int b = 0; b < N_BASIS; b++)
                s += coeffs2[r * N_BASIS + b] * bases2[b * D_HID * N_CLASS + i];
            g_W2[r * D_HID * N_CLASS + i] = s;
        }
    }
}

__global__ void k_zero_cnt()
{
    int i = blockIdx.x * blockDim.x + threadIdx.x;
    if (i < N_REL * N_NODES) g_cnt[i] = 0;
}

__global__ void k_count(const int* __restrict__ ei, const int* __restrict__ et)
{
    int e = blockIdx.x * blockDim.x + threadIdx.x;
    if (e >= N_EDGES) return;
    int dst = __ldg(&ei[N_EDGES + e]);
    int t   = __ldg(&et[e]);
    atomicAdd(&g_cnt[t * N_NODES + dst], 1);
}

// ---------------- GEMM: T[r] = X @ W_r (r<16), self-term (r==16) ----------------
// k-major smem X tile: xs[k][m]. Thread owns 4 consecutive rows (m = lane*4..+3)
// -> per k-iter: 1 LDS.128 (x) + 2 broadcast LDS.128 (w) + 16 FFMA2.
template<int LAYER>
__global__ __launch_bounds__(256) void k_gemm(const float* __restrict__ Xin,
                                              const float* __restrict__ Wself,
                                              float* __restrict__ selfout_l2)
{
    constexpr int NOUT = (LAYER == 1) ? D_HID : N_CLASS;
    constexpr int TO   = (LAYER == 1) ? 8 : 2;      // outputs per thread (8 warps cover NOUT)

    __shared__ float xs[64][128];                   // 32 KB, k-major
    __shared__ float ws[64 * NOUT];

    const float* X    = (LAYER == 1) ? Xin  : g_h;
    const float* Wrel = (LAYER == 1) ? g_W1 : g_W2;
    float*       Trel = (LAYER == 1) ? g_T1 : g_T2;
    float*       selfdst = (LAYER == 1) ? g_h : selfout_l2;

    const int r  = blockIdx.y;
    const float* W = (r < N_REL) ? (Wrel + (size_t)r * 64 * NOUT) : Wself;
    const int nb = blockIdx.x * 128;

    // load X tile transposed into k-major smem
    for (int t = threadIdx.x; t < 128 * 16; t += 256) {
        int m = t & 127;
        int g = t >> 7;            // 0..15, column group of 4
        float4 v = make_float4(0.f, 0.f, 0.f, 0.f);
        int node = nb + m;
        if (node < N_NODES) v = *(const float4*)(X + (size_t)node * 64 + g * 4);
        if (LAYER == 2) {
            v.x = fmaxf(v.x, 0.f); v.y = fmaxf(v.y, 0.f);
            v.z = fmaxf(v.z, 0.f); v.w = fmaxf(v.w, 0.f);
        }
        xs[g * 4 + 0][m] = v.x;
        xs[g * 4 + 1][m] = v.y;
        xs[g * 4 + 2][m] = v.z;
        xs[g * 4 + 3][m] = v.w;
    }
    // load W tile
    for (int i = threadIdx.x * 4; i < 64 * NOUT; i += 256 * 4) {
        *(float4*)(ws + i) = *(const float4*)(W + i);
    }
    __syncthreads();

    const int lane = threadIdx.x & 31;
    const int og   = threadIdx.x >> 5;      // warp id, 0..7
    const int o0   = og * TO;
    const int m0   = lane * 4;

    unsigned long long acc[4][TO / 2];
    #pragma unroll
    for (int i = 0; i < 4; i++)
        #pragma unroll
        for (int j = 0; j < TO / 2; j++) acc[i][j] = 0ull;

    #pragma unroll 8
    for (int k = 0; k < 64; k++) {
        float4 xv = *(const float4*)&xs[k][m0];         // LDS.128, conflict-free
        unsigned long long x2[4];
        asm("mov.b64 %0, {%1, %1};" : "=l"(x2[0]) : "f"(xv.x));
        asm("mov.b64 %0, {%1, %1};" : "=l"(x2[1]) : "f"(xv.y));
        asm("mov.b64 %0, {%1, %1};" : "=l"(x2[2]) : "f"(xv.z));
        asm("mov.b64 %0, {%1, %1};" : "=l"(x2[3]) : "f"(xv.w));

        if (TO == 8) {
            float4 wa = *(const float4*)(ws + k * NOUT + o0);       // broadcast LDS.128
            float4 wb = *(const float4*)(ws + k * NOUT + o0 + 4);
            unsigned long long w2[4];
            asm("mov.b64 %0, {%1, %2};" : "=l"(w2[0]) : "f"(wa.x), "f"(wa.y));
            asm("mov.b64 %0, {%1, %2};" : "=l"(w2[1]) : "f"(wa.z), "f"(wa.w));
            asm("mov.b64 %0, {%1, %2};" : "=l"(w2[2]) : "f"(wb.x), "f"(wb.y));
            asm("mov.b64 %0, {%1, %2};" : "=l"(w2[3]) : "f"(wb.z), "f"(wb.w));
            #pragma unroll
            for (int j = 0; j < 4; j++)
                #pragma unroll
                for (int i = 0; i < 4; i++)
                    asm("fma.rn.f32x2 %0, %1, %2, %0;" : "+l"(acc[i][j]) : "l"(x2[i]), "l"(w2[j]));
        } else {
            float2 wa = *(const float2*)(ws + k * NOUT + o0);       // broadcast LDS.64
            unsigned long long w2;
            asm("mov.b64 %0, {%1, %2};" : "=l"(w2) : "f"(wa.x), "f"(wa.y));
            #pragma unroll
            for (int i = 0; i < 4; i++)
                asm("fma.rn.f32x2 %0, %1, %2, %0;" : "+l"(acc[i][0]) : "l"(x2[i]), "l"(w2));
        }
    }

    float* outbase = (r < N_REL) ? (Trel + ((size_t)r * N_NODES + nb) * NOUT)
                                 : (selfdst + (size_t)nb * NOUT);
    #pragma unroll
    for (int i = 0; i < 4; i++) {
        int m = m0 + i;
        if (nb + m < N_NODES) {
            float* op = outbase + (size_t)m * NOUT + o0;
            if (TO == 8) {
                float2 a = *(float2*)&acc[i][0];
                float2 b = *(float2*)&acc[i][1];
                float2 c = *(float2*)&acc[i][2];
                float2 d = *(float2*)&acc[i][3];
                *(float4*)(op)     = make_float4(a.x, a.y, b.x, b.y);
                *(float4*)(op + 4) = make_float4(c.x, c.y, d.x, d.y);
            } else {
                *(float2*)op = *(float2*)&acc[i][0];
            }
        }
    }
}

// ---------------- edge scatter: dest[dst] += inv_c * T[type][src] ----------------
template<int LAYER>
__global__ void k_scatter(const int* __restrict__ ei,
                          const int* __restrict__ et,
                          float* __restrict__ dest_l2)
{
    constexpr int NOUT = (LAYER == 1) ? D_HID : N_CLASS;
    constexpr int CH   = NOUT / 4;
    const float* T = (LAYER == 1) ? g_T1 : g_T2;
    float* dest    = (LAYER == 1) ? g_h  : dest_l2;

    int idx = blockIdx.x * blockDim.x + threadIdx.x;
    if (idx >= N_EDGES * CH) return;
    int e = idx / CH;
    int c = idx & (CH - 1);

    int src = __ldg(&ei[e]);
    int dst = __ldg(&ei[N_EDGES + e]);
    int t   = __ldg(&et[e]);
    int cnt = __ldg((const int*)&g_cnt[t * N_NODES + dst]);
    float inv = 1.0f / (float)(cnt > 0 ? cnt : 1);

    float4 v = __ldg((const float4*)(T + ((size_t)t * N_NODES + src) * NOUT + c * 4));
    float* p = dest + (size_t)dst * NOUT + c * 4;
    asm volatile("red.global.add.v4.f32 [%0], {%1, %2, %3, %4};"
                 :: "l"(p), "f"(v.x * inv), "f"(v.y * inv), "f"(v.z * inv), "f"(v.w * inv)
                 : "memory");
}

// ---------------- launch ----------------
extern "C" void kernel_launch(void* const* d_in, const int* in_sizes, int n_in,
                              void* d_out, int out_size)
{
    const float* x       = (const float*)d_in[0];
    const float* bases1  = (const float*)d_in[1];
    const float* coeffs1 = (const float*)d_in[2];
    const float* self1   = (const float*)d_in[3];
    const float* bases2  = (const float*)d_in[4];
    const float* coeffs2 = (const float*)d_in[5];
    const float* self2   = (const float*)d_in[6];
    const int* ei        = (const int*)d_in[7];
    const int* et        = (const int*)d_in[8];
    float* out = (float*)d_out;

    const int NODE_TILES = (N_NODES + 127) / 128;   // 391

    k_weights<<<32, 256>>>(bases1, coeffs1, bases2, coeffs2);
    k_zero_cnt<<<(N_REL * N_NODES + 255) / 256, 256>>>();
    k_count<<<(N_EDGES + 255) / 256, 256>>>(ei, et);

    // layer 1: T1[r] = x @ W1_r ; h = x @ self1 ; then scatter into h
    k_gemm<1><<<dim3(NODE_TILES, N_REL + 1), 256>>>(x, self1, nullptr);
    k_scatter<1><<<(N_EDGES * (D_HID / 4) + 255) / 256, 256>>>(ei, et, nullptr);

    // layer 2: reads relu(h) inside; T2[r] = relu(h) @ W2_r ; out = relu(h) @ self2 ; scatter into out
    k_gemm<2><<<dim3(NODE_TILES, N_REL + 1), 256>>>(nullptr, self2, out);
    k_scatter<2><<<(N_EDGES * (N_CLASS / 4) + 255) / 256, 256>>>(ei, et, out);
}

// round 5
// speedup vs baseline: 1.0749x; 1.0749x over previous
#include <cuda_runtime.h>
#include <cstdint>

#define N_NODES 50000
#define N_REL   16
#define N_BASIS 8
#define D_IN    64
#define D_HID   64
#define N_CLASS 16
#define N_EDGES 800000

// ---------------- device scratch (static, allowed) ----------------
__device__ __align__(16) float g_W1[N_REL * D_IN * D_HID];      // 256 KB
__device__ __align__(16) float g_W2[N_REL * D_HID * N_CLASS];   // 64 KB
__device__ __align__(16) float g_T1[N_REL * N_NODES * D_HID];   // 204.8 MB
__device__ __align__(16) float g_T2[N_REL * N_NODES * N_CLASS]; // 51.2 MB
__device__ __align__(16) float g_h [N_NODES * D_HID];           // 12.8 MB
__device__ __align__(16) int   g_cnt[N_REL * N_NODES];          // 3.2 MB
__device__ __align__(16) float g_inv[N_EDGES];                  // 3.2 MB

// ---------------- tiny setup kernels ----------------
__global__ void k_weights(const float* __restrict__ bases1, const float* __restrict__ coeffs1,
                          const float* __restrict__ bases2, const float* __restrict__ coeffs2)
{
    int blk = blockIdx.x;
    int r = blk & 15;
    if (blk < 16) {
        for (int i = threadIdx.x; i < D_IN * D_HID; i += blockDim.x) {
            float s = 0.f;
            #pragma unroll
            for (int b = 0; b < N_BASIS; b++)
                s += coeffs1[r * N_BASIS + b] * bases1[b * D_IN * D_HID + i];
            g_W1[r * D_IN * D_HID + i] = s;
        }
    } else {
        for (int i = threadIdx.x; i < D_HID * N_CLASS; i += blockDim.x) {
            float s = 0.f;
            #pragma unroll
            for (int b = 0; b < N_BASIS; b++)
                s += coeffs2[r * N_BASIS + b] * bases2[b * D_HID * N_CLASS + i];
            g_W2[r * D_HID * N_CLASS + i] = s;
        }
    }
}

__global__ void k_zero_cnt()
{
    int i = blockIdx.x * blockDim.x + threadIdx.x;
    if (i < N_REL * N_NODES) g_cnt[i] = 0;
}

__global__ void k_count(const int* __restrict__ ei, const int* __restrict__ et)
{
    int e = blockIdx.x * blockDim.x + threadIdx.x;
    if (e >= N_EDGES) return;
    int dst = __ldg(&ei[N_EDGES + e]);
    int t   = __ldg(&et[e]);
    atomicAdd(&g_cnt[t * N_NODES + dst], 1);
}

__global__ void k_inv(const int* __restrict__ ei, const int* __restrict__ et)
{
    int e = blockIdx.x * blockDim.x + threadIdx.x;
    if (e >= N_EDGES) return;
    int dst = __ldg(&ei[N_EDGES + e]);
    int t   = __ldg(&et[e]);
    int cnt = g_cnt[t * N_NODES + dst];
    g_inv[e] = 1.0f / (float)(cnt > 0 ? cnt : 1);
}

// ---------------- GEMM: T[r] = X @ W_r (r<16), self-term (r==16) ----------------
// 4 warps/block; warp w covers o-slice [w*TO, w*TO+TO); lanes cover all 128 m rows
// (m = lane*4). Per k: 1 LDS.128 x (512 B/warp) + TO/4 broadcast LDS.128 w.
template<int LAYER>
__global__ __launch_bounds__(128) void k_gemm(const float* __restrict__ Xin,
                                              const float* __restrict__ Wself,
                                              float* __restrict__ selfout_l2)
{
    constexpr int NOUT = (LAYER == 1) ? D_HID : N_CLASS;
    constexpr int TO   = (LAYER == 1) ? 16 : 4;     // o per warp (4 warps cover NOUT)
    constexpr int NW2  = TO / 2;                    // u64 accumulators per m-row

    __shared__ float xs[64][128];                   // 32 KB, k-major
    __shared__ float ws[64 * NOUT];                 // 16 KB / 4 KB

    const float* X    = (LAYER == 1) ? Xin  : g_h;
    const float* Wrel = (LAYER == 1) ? g_W1 : g_W2;
    float*       Trel = (LAYER == 1) ? g_T1 : g_T2;
    float*       selfdst = (LAYER == 1) ? g_h : selfout_l2;

    const int r  = blockIdx.y;
    const float* W = (r < N_REL) ? (Wrel + (size_t)r * 64 * NOUT) : Wself;
    const int nb = blockIdx.x * 128;

    // load X tile transposed into k-major smem
    for (int t = threadIdx.x; t < 128 * 16; t += 128) {
        int m = t & 127;
        int g = t >> 7;            // 0..15
        float4 v = make_float4(0.f, 0.f, 0.f, 0.f);
        int node = nb + m;
        if (node < N_NODES) v = *(const float4*)(X + (size_t)node * 64 + g * 4);
        if (LAYER == 2) {
            v.x = fmaxf(v.x, 0.f); v.y = fmaxf(v.y, 0.f);
            v.z = fmaxf(v.z, 0.f); v.w = fmaxf(v.w, 0.f);
        }
        xs[g * 4 + 0][m] = v.x;
        xs[g * 4 + 1][m] = v.y;
        xs[g * 4 + 2][m] = v.z;
        xs[g * 4 + 3][m] = v.w;
    }
    // load W tile
    for (int i = threadIdx.x * 4; i < 64 * NOUT; i += 128 * 4) {
        *(float4*)(ws + i) = *(const float4*)(W + i);
    }
    __syncthreads();

    const int lane = threadIdx.x & 31;
    const int og   = threadIdx.x >> 5;      // warp id 0..3
    const int o0   = og * TO;
    const int m0   = lane * 4;

    unsigned long long acc[4][NW2];
    #pragma unroll
    for (int i = 0; i < 4; i++)
        #pragma unroll
        for (int j = 0; j < NW2; j++) acc[i][j] = 0ull;

    #pragma unroll 4
    for (int k = 0; k < 64; k++) {
        float4 xv = *(const float4*)&xs[k][m0];         // LDS.128
        unsigned long long x2[4];
        asm("mov.b64 %0, {%1, %1};" : "=l"(x2[0]) : "f"(xv.x));
        asm("mov.b64 %0, {%1, %1};" : "=l"(x2[1]) : "f"(xv.y));
        asm("mov.b64 %0, {%1, %1};" : "=l"(x2[2]) : "f"(xv.z));
        asm("mov.b64 %0, {%1, %1};" : "=l"(x2[3]) : "f"(xv.w));

        unsigned long long w2[NW2];
        #pragma unroll
        for (int q = 0; q < TO / 4; q++) {
            float4 wa = *(const float4*)(ws + k * NOUT + o0 + q * 4);   // broadcast
            asm("mov.b64 %0, {%1, %2};" : "=l"(w2[q * 2 + 0]) : "f"(wa.x), "f"(wa.y));
            asm("mov.b64 %0, {%1, %2};" : "=l"(w2[q * 2 + 1]) : "f"(wa.z), "f"(wa.w));
        }
        #pragma unroll
        for (int j = 0; j < NW2; j++)
            #pragma unroll
            for (int i = 0; i < 4; i++)
                asm("fma.rn.f32x2 %0, %1, %2, %0;" : "+l"(acc[i][j]) : "l"(x2[i]), "l"(w2[j]));
    }

    float* outbase = (r < N_REL) ? (Trel + ((size_t)r * N_NODES + nb) * NOUT)
                                 : (selfdst + (size_t)nb * NOUT);
    #pragma unroll
    for (int i = 0; i < 4; i++) {
        int m = m0 + i;
        if (nb + m < N_NODES) {
            float* op = outbase + (size_t)m * NOUT + o0;
            #pragma unroll
            for (int j = 0; j < NW2; j += 2) {
                float2 a = *(float2*)&acc[i][j];
                float2 b = *(float2*)&acc[i][j + 1];
                *(float4*)(op + 2 * j) = make_float4(a.x, a.y, b.x, b.y);
            }
        }
    }
}

// ---------------- edge scatter: dest[dst] += inv_c * T[type][src] ----------------
template<int LAYER>
__global__ void k_scatter(const int* __restrict__ ei,
                          const int* __restrict__ et,
                          float* __restrict__ dest_l2)
{
    constexpr int NOUT = (LAYER == 1) ? D_HID : N_CLASS;
    constexpr int CH   = NOUT / 4;
    const float* T = (LAYER == 1) ? g_T1 : g_T2;
    float* dest    = (LAYER == 1) ? g_h  : dest_l2;

    int idx = blockIdx.x * blockDim.x + threadIdx.x;
    if (idx >= N_EDGES * CH) return;
    int e = idx / CH;
    int c = idx & (CH - 1);

    int src = __ldg(&ei[e]);
    int dst = __ldg(&ei[N_EDGES + e]);
    int t   = __ldg(&et[e]);
    float inv = __ldg(&g_inv[e]);

    float4 v = __ldg((const float4*)(T + ((size_t)t * N_NODES + src) * NOUT + c * 4));
    float* p = dest + (size_t)dst * NOUT + c * 4;
    asm volatile("red.global.add.v4.f32 [%0], {%1, %2, %3, %4};"
                 :: "l"(p), "f"(v.x * inv), "f"(v.y * inv), "f"(v.z * inv), "f"(v.w * inv)
                 : "memory");
}

// ---------------- launch ----------------
extern "C" void kernel_launch(void* const* d_in, const int* in_sizes, int n_in,
                              void* d_out, int out_size)
{
    const float* x       = (const float*)d_in[0];
    const float* bases1  = (const float*)d_in[1];
    const float* coeffs1 = (const float*)d_in[2];
    const float* self1   = (const float*)d_in[3];
    const float* bases2  = (const float*)d_in[4];
    const float* coeffs2 = (const float*)d_in[5];
    const float* self2   = (const float*)d_in[6];
    const int* ei        = (const int*)d_in[7];
    const int* et        = (const int*)d_in[8];
    float* out = (float*)d_out;

    const int NODE_TILES = (N_NODES + 127) / 128;   // 391

    k_weights<<<32, 256>>>(bases1, coeffs1, bases2, coeffs2);
    k_zero_cnt<<<(N_REL * N_NODES + 255) / 256, 256>>>();
    k_count<<<(N_EDGES + 255) / 256, 256>>>(ei, et);
    k_inv<<<(N_EDGES + 255) / 256, 256>>>(ei, et);

    // layer 1: T1[r] = x @ W1_r ; h = x @ self1 ; then scatter into h
    k_gemm<1><<<dim3(NODE_TILES, N_REL + 1), 128>>>(x, self1, nullptr);
    k_scatter<1><<<(N_EDGES * (D_HID / 4) + 255) / 256, 256>>>(ei, et, nullptr);

    // layer 2: reads relu(h) inside; T2[r] = relu(h) @ W2_r ; out = relu(h) @ self2 ; scatter into out
    k_gemm<2><<<dim3(NODE_TILES, N_REL + 1), 128>>>(nullptr, self2, out);
    k_scatter<2><<<(N_EDGES * (N_CLASS / 4) + 255) / 256, 256>>>(ei, et, out);
}

// round 6
// speedup vs baseline: 1.2178x; 1.1329x over previous
#include <cuda_runtime.h>
#include <cstdint>

#define N_NODES 50000
#define N_REL   16
#define N_BASIS 8
#define D_IN    64
#define D_HID   64
#define N_CLASS 16
#define N_EDGES 800000

// padded sorted-edge capacity: 16 bins each padded to multiple of 128
#define ES      802176              // 6267 * 128 >= 800000 + 16*127
#define NBLK_E  6267

// ---------------- device scratch ----------------
__device__ __align__(16) float g_W1[N_REL * D_IN * D_HID];      // 256 KB
__device__ __align__(16) float g_W2[N_REL * D_HID * N_CLASS];   // 64 KB
__device__ __align__(16) float g_h [N_NODES * D_HID];           // 12.8 MB
__device__ __align__(16) int   g_cnt[N_REL * N_NODES];          // 3.2 MB
__device__ int   g_hist[N_REL];
__device__ int   g_padoff[N_REL + 1];
__device__ int   g_sortpos[N_REL];
__device__ __align__(16) int   g_s[ES];
__device__ __align__(16) int   g_d[ES];
__device__ __align__(16) float g_v[ES];

// ---------------- setup ----------------
__global__ void k_weights(const float* __restrict__ bases1, const float* __restrict__ coeffs1,
                          const float* __restrict__ bases2, const float* __restrict__ coeffs2)
{
    int blk = blockIdx.x;
    int r = blk & 15;
    if (blk < 16) {
        for (int i = threadIdx.x; i < D_IN * D_HID; i += blockDim.x) {
            float s = 0.f;
            #pragma unroll
            for (int b = 0; b < N_BASIS; b++)
                s += coeffs1[r * N_BASIS + b] * bases1[b * D_IN * D_HID + i];
            g_W1[r * D_IN * D_HID + i] = s;
        }
    } else {
        for (int i = threadIdx.x; i < D_HID * N_CLASS; i += blockDim.x) {
            float s = 0.f;
            #pragma unroll
            for (int b = 0; b < N_BASIS; b++)
                s += coeffs2[r * N_BASIS + b] * bases2[b * D_HID * N_CLASS + i];
            g_W2[r * D_HID * N_CLASS + i] = s;
        }
    }
}

__global__ void k_zero()
{
    int i = blockIdx.x * blockDim.x + threadIdx.x;
    if (i < N_REL * N_NODES) g_cnt[i] = 0;
    if (i < ES) { g_s[i] = 0; g_d[i] = 0; g_v[i] = 0.f; }
}

__global__ void k_count(const int* __restrict__ ei, const int* __restrict__ et)
{
    int e = blockIdx.x * blockDim.x + threadIdx.x;
    if (e >= N_EDGES) return;
    int dst = __ldg(&ei[N_EDGES + e]);
    int t   = __ldg(&et[e]);
    atomicAdd(&g_cnt[t * N_NODES + dst], 1);
}

// per-relation histogram by reduction over g_cnt (no contended atomics)
__global__ void k_hist16()
{
    __shared__ int red[256];
    int r = blockIdx.x;
    int s = 0;
    for (int i = threadIdx.x; i < N_NODES; i += 256) s += g_cnt[r * N_NODES + i];
    red[threadIdx.x] = s;
    __syncthreads();
    for (int w = 128; w > 0; w >>= 1) {
        if (threadIdx.x < w) red[threadIdx.x] += red[threadIdx.x + w];
        __syncthreads();
    }
    if (threadIdx.x == 0) g_hist[r] = red[0];
}

__global__ void k_scan()
{
    if (threadIdx.x == 0 && blockIdx.x == 0) {
        int off = 0;
        for (int r = 0; r < N_REL; r++) {
            g_padoff[r] = off;
            g_sortpos[r] = off;
            off += ((g_hist[r] + 127) & ~127);
        }
        g_padoff[N_REL] = off;
    }
}

// warp-aggregated counting-sort permute; also computes inv
__global__ void k_permute(const int* __restrict__ ei, const int* __restrict__ et)
{
    int e = blockIdx.x * blockDim.x + threadIdx.x;
    if (e >= N_EDGES) return;
    int src = __ldg(&ei[e]);
    int dst = __ldg(&ei[N_EDGES + e]);
    int t   = __ldg(&et[e]);
    int lane = threadIdx.x & 31;

    unsigned mask = __match_any_sync(__activemask(), t);
    int leader = __ffs(mask) - 1;
    int rank   = __popc(mask & ((1u << lane) - 1));
    int base = 0;
    if (lane == leader) base = atomicAdd(&g_sortpos[t], __popc(mask));
    base = __shfl_sync(__activemask(), base, leader);
    int pos = base + rank;

    int cnt = g_cnt[t * N_NODES + dst];
    g_s[pos] = src;
    g_d[pos] = dst;
    g_v[pos] = 1.0f / (float)(cnt > 0 ? cnt : 1);
}

// ---------------- dense self-term GEMM: OUT = act(X) @ W ----------------
template<int NOUT, bool RELU>
__global__ __launch_bounds__(128) void k_dense(const float* __restrict__ X,
                                               const float* __restrict__ W,
                                               float* __restrict__ OUT)
{
    constexpr int TO  = NOUT / 4;       // per-warp o-slice (4 warps)
    constexpr int NW2 = TO / 2;

    __shared__ float xs[64][128];
    __shared__ float ws[64 * NOUT];

    const int nb = blockIdx.x * 128;

    for (int t = threadIdx.x; t < 128 * 16; t += 128) {
        int m = t & 127;
        int g = t >> 7;
        float4 v = make_float4(0.f, 0.f, 0.f, 0.f);
        int node = nb + m;
        if (node < N_NODES) v = *(const float4*)(X + (size_t)node * 64 + g * 4);
        if (RELU) {
            v.x = fmaxf(v.x, 0.f); v.y = fmaxf(v.y, 0.f);
            v.z = fmaxf(v.z, 0.f); v.w = fmaxf(v.w, 0.f);
        }
        xs[g * 4 + 0][m] = v.x;
        xs[g * 4 + 1][m] = v.y;
        xs[g * 4 + 2][m] = v.z;
        xs[g * 4 + 3][m] = v.w;
    }
    for (int i = threadIdx.x * 4; i < 64 * NOUT; i += 128 * 4)
        *(float4*)(ws + i) = *(const float4*)(W + i);
    __syncthreads();

    const int lane = threadIdx.x & 31;
    const int og   = threadIdx.x >> 5;
    const int o0   = og * TO;
    const int m0   = lane * 4;

    unsigned long long acc[4][NW2];
    #pragma unroll
    for (int i = 0; i < 4; i++)
        #pragma unroll
        for (int j = 0; j < NW2; j++) acc[i][j] = 0ull;

    #pragma unroll 4
    for (int k = 0; k < 64; k++) {
        float4 xv = *(const float4*)&xs[k][m0];
        unsigned long long x2[4];
        asm("mov.b64 %0, {%1, %1};" : "=l"(x2[0]) : "f"(xv.x));
        asm("mov.b64 %0, {%1, %1};" : "=l"(x2[1]) : "f"(xv.y));
        asm("mov.b64 %0, {%1, %1};" : "=l"(x2[2]) : "f"(xv.z));
        asm("mov.b64 %0, {%1, %1};" : "=l"(x2[3]) : "f"(xv.w));
        unsigned long long w2[NW2];
        #pragma unroll
        for (int q = 0; q < TO / 4; q++) {
            float4 wa = *(const float4*)(ws + k * NOUT + o0 + q * 4);
            asm("mov.b64 %0, {%1, %2};" : "=l"(w2[q * 2 + 0]) : "f"(wa.x), "f"(wa.y));
            asm("mov.b64 %0, {%1, %2};" : "=l"(w2[q * 2 + 1]) : "f"(wa.z), "f"(wa.w));
        }
        #pragma unroll
        for (int j = 0; j < NW2; j++)
            #pragma unroll
            for (int i = 0; i < 4; i++)
                asm("fma.rn.f32x2 %0, %1, %2, %0;" : "+l"(acc[i][j]) : "l"(x2[i]), "l"(w2[j]));
    }

    #pragma unroll
    for (int i = 0; i < 4; i++) {
        int m = m0 + i;
        if (nb + m < N_NODES) {
            float* op = OUT + (size_t)(nb + m) * NOUT + o0;
            #pragma unroll
            for (int j = 0; j < NW2; j += 2) {
                float2 a = *(float2*)&acc[i][j];
                float2 b = *(float2*)&acc[i][j + 1];
                *(float4*)(op + 2 * j) = make_float4(a.x, a.y, b.x, b.y);
            }
        }
    }
}

// ---------------- fused gather-GEMM-scatter over relation-sorted edges ----------------
// block = 128 edges of one relation; msg = X[src] @ W_r, dest[dst] += inv * msg
template<int NOUT, bool RELU>
__global__ __launch_bounds__(128) void k_fused(const float* __restrict__ X,
                                               const float* __restrict__ Wrel,
                                               float* __restrict__ dest)
{
    constexpr int TO  = NOUT / 4;
    constexpr int NW2 = TO / 2;

    __shared__ float xs[64][128];
    __shared__ float ws[64 * NOUT];
    __shared__ int   ds[128];
    __shared__ float vs[128];

    const int b0 = blockIdx.x * 128;

    // relation of this block (bins are 128-aligned)
    int r = 0;
    #pragma unroll
    for (int i = 1; i < N_REL; i++)
        if (b0 >= __ldg(&g_padoff[i])) r = i;

    // stage this thread's edge
    {
        int t = threadIdx.x;
        int slot = b0 + t;
        int src = g_s[slot];
        ds[t] = g_d[slot];
        vs[t] = g_v[slot];
        const float* xrow = X + (size_t)src * 64;
        #pragma unroll
        for (int g = 0; g < 16; g++) {
            float4 v = __ldg((const float4*)(xrow + g * 4));
            if (RELU) {
                v.x = fmaxf(v.x, 0.f); v.y = fmaxf(v.y, 0.f);
                v.z = fmaxf(v.z, 0.f); v.w = fmaxf(v.w, 0.f);
            }
            xs[g * 4 + 0][t] = v.x;
            xs[g * 4 + 1][t] = v.y;
            xs[g * 4 + 2][t] = v.z;
            xs[g * 4 + 3][t] = v.w;
        }
    }
    const float* W = Wrel + (size_t)r * 64 * NOUT;
    for (int i = threadIdx.x * 4; i < 64 * NOUT; i += 128 * 4)
        *(float4*)(ws + i) = *(const float4*)(W + i);
    __syncthreads();

    const int lane = threadIdx.x & 31;
    const int og   = threadIdx.x >> 5;
    const int o0   = og * TO;
    const int m0   = lane * 4;

    unsigned long long acc[4][NW2];
    #pragma unroll
    for (int i = 0; i < 4; i++)
        #pragma unroll
        for (int j = 0; j < NW2; j++) acc[i][j] = 0ull;

    #pragma unroll 4
    for (int k = 0; k < 64; k++) {
        float4 xv = *(const float4*)&xs[k][m0];
        unsigned long long x2[4];
        asm("mov.b64 %0, {%1, %1};" : "=l"(x2[0]) : "f"(xv.x));
        asm("mov.b64 %0, {%1, %1};" : "=l"(x2[1]) : "f"(xv.y));
        asm("mov.b64 %0, {%1, %1};" : "=l"(x2[2]) : "f"(xv.z));
        asm("mov.b64 %0, {%1, %1};" : "=l"(x2[3]) : "f"(xv.w));
        unsigned long long w2[NW2];
        #pragma unroll
        for (int q = 0; q < TO / 4; q++) {
            float4 wa = *(const float4*)(ws + k * NOUT + o0 + q * 4);
            asm("mov.b64 %0, {%1, %2};" : "=l"(w2[q * 2 + 0]) : "f"(wa.x), "f"(wa.y));
            asm("mov.b64 %0, {%1, %2};" : "=l"(w2[q * 2 + 1]) : "f"(wa.z), "f"(wa.w));
        }
        #pragma unroll
        for (int j = 0; j < NW2; j++)
            #pragma unroll
            for (int i = 0; i < 4; i++)
                asm("fma.rn.f32x2 %0, %1, %2, %0;" : "+l"(acc[i][j]) : "l"(x2[i]), "l"(w2[j]));
    }

    // epilogue: scale by inv, atomic-reduce into dest[dst]
    #pragma unroll
    for (int i = 0; i < 4; i++) {
        int m = m0 + i;
        float inv = vs[m];
        float* op = dest + (size_t)ds[m] * NOUT + o0;
        #pragma unroll
        for (int j = 0; j < NW2; j += 2) {
            float2 a = *(float2*)&acc[i][j];
            float2 b = *(float2*)&acc[i][j + 1];
            asm volatile("red.global.add.v4.f32 [%0], {%1, %2, %3, %4};"
                         :: "l"(op + 2 * j),
                            "f"(a.x * inv), "f"(a.y * inv), "f"(b.x * inv), "f"(b.y * inv)
                         : "memory");
        }
    }
}

// ---------------- launch ----------------
extern "C" void kernel_launch(void* const* d_in, const int* in_sizes, int n_in,
                              void* d_out, int out_size)
{
    const float* x       = (const float*)d_in[0];
    const float* bases1  = (const float*)d_in[1];
    const float* coeffs1 = (const float*)d_in[2];
    const float* self1   = (const float*)d_in[3];
    const float* bases2  = (const float*)d_in[4];
    const float* coeffs2 = (const float*)d_in[5];
    const float* self2   = (const float*)d_in[6];
    const int* ei        = (const int*)d_in[7];
    const int* et        = (const int*)d_in[8];
    float* out = (float*)d_out;

    const int NODE_TILES = (N_NODES + 127) / 128;   // 391

    float* w1p; cudaGetSymbolAddress((void**)&w1p, g_W1);
    float* w2p; cudaGetSymbolAddress((void**)&w2p, g_W2);
    float* hp;  cudaGetSymbolAddress((void**)&hp,  g_h);

    k_weights<<<32, 256>>>(bases1, coeffs1, bases2, coeffs2);
    k_zero<<<(ES + 255) / 256, 256>>>();
    k_count<<<(N_EDGES + 255) / 256, 256>>>(ei, et);
    k_hist16<<<16, 256>>>();
    k_scan<<<1, 32>>>();
    k_permute<<<(N_EDGES + 255) / 256, 256>>>(ei, et);

    // layer 1: h = x @ self1, then h[dst] += inv * (x[src] @ W1_r)
    k_dense<D_HID, false><<<NODE_TILES, 128>>>(x, self1, hp);
    k_fused<D_HID, false><<<NBLK_E, 128>>>(x, w1p, hp);

    // layer 2: out = relu(h) @ self2, then out[dst] += inv * (relu(h[src]) @ W2_r)
    k_dense<N_CLASS, true><<<NODE_TILES, 128>>>(hp, self2, out);
    k_fused<N_CLASS, true><<<NBLK_E, 128>>>(hp, w2p, out);
}

// round 7
// speedup vs baseline: 1.2246x; 1.0056x over previous
#include <cuda_runtime.h>
#include <cstdint>

#define N_NODES 50000
#define N_REL   16
#define N_BASIS 8
#define D_IN    64
#define D_HID   64
#define N_CLASS 16
#define N_EDGES 800000

// padded sorted-edge capacity: 16 bins each padded to multiple of 128
#define ES      802176              // 6267 * 128
#define NBLK_E  6267

// ---------------- device scratch ----------------
__device__ __align__(16) float g_W1[N_REL * D_IN * D_HID];      // 256 KB
__device__ __align__(16) float g_W2[N_REL * D_HID * N_CLASS];   // 64 KB
__device__ __align__(16) float g_h [N_NODES * D_HID];           // 12.8 MB
__device__ __align__(16) int   g_cnt[N_REL * N_NODES];          // 3.2 MB
__device__ int   g_hist[N_REL];
__device__ int   g_sortrel[N_REL];          // per-relation cursor (relative)
__device__ __align__(16) int   g_s[ES];
__device__ __align__(16) int   g_d[ES];
__device__ __align__(16) float g_v[ES];

// ---------------- init: weights + zero all mutable state ----------------
__global__ void k_init(const float* __restrict__ bases1, const float* __restrict__ coeffs1,
                       const float* __restrict__ bases2, const float* __restrict__ coeffs2)
{
    int bid = blockIdx.x;
    // blocks 0..15: W1_r ; 16..31: W2_r
    if (bid < 16) {
        int r = bid;
        float c[N_BASIS];
        #pragma unroll
        for (int b = 0; b < N_BASIS; b++) c[b] = coeffs1[r * N_BASIS + b];
        for (int i = threadIdx.x; i < D_IN * D_HID; i += blockDim.x) {
            float s = 0.f;
            #pragma unroll
            for (int b = 0; b < N_BASIS; b++) s += c[b] * bases1[b * D_IN * D_HID + i];
            g_W1[r * D_IN * D_HID + i] = s;
        }
    } else if (bid < 32) {
        int r = bid - 16;
        float c[N_BASIS];
        #pragma unroll
        for (int b = 0; b < N_BASIS; b++) c[b] = coeffs2[r * N_BASIS + b];
        for (int i = threadIdx.x; i < D_HID * N_CLASS; i += blockDim.x) {
            float s = 0.f;
            #pragma unroll
            for (int b = 0; b < N_BASIS; b++) s += c[b] * bases2[b * D_HID * N_CLASS + i];
            g_W2[r * D_HID * N_CLASS + i] = s;
        }
    }
    // all blocks: grid-stride zeroing
    int nthreads = gridDim.x * blockDim.x;
    int gt = bid * blockDim.x + threadIdx.x;
    for (int i = gt; i < N_REL * N_NODES; i += nthreads) g_cnt[i] = 0;
    for (int i = gt; i < ES; i += nthreads) { g_s[i] = 0; g_d[i] = 0; g_v[i] = 0.f; }
    for (int i = gt; i < N_NODES * D_HID / 4; i += nthreads)
        ((float4*)g_h)[i] = make_float4(0.f, 0.f, 0.f, 0.f);
    if (gt < N_REL) { g_hist[gt] = 0; g_sortrel[gt] = 0; }
}

// ---------------- count per-(rel,dst) + per-rel histogram ----------------
__global__ void k_counthist(const int* __restrict__ ei, const int* __restrict__ et)
{
    __shared__ int lh[N_REL];
    if (threadIdx.x < N_REL) lh[threadIdx.x] = 0;
    __syncthreads();
    int e = blockIdx.x * blockDim.x + threadIdx.x;
    if (e < N_EDGES) {
        int dst = __ldg(&ei[N_EDGES + e]);
        int t   = __ldg(&et[e]);
        atomicAdd(&g_cnt[t * N_NODES + dst], 1);
        atomicAdd(&lh[t], 1);
    }
    __syncthreads();
    if (threadIdx.x < N_REL && lh[threadIdx.x] > 0)
        atomicAdd(&g_hist[threadIdx.x], lh[threadIdx.x]);
}

// ---------------- counting-sort permute (inline scan) + inv ----------------
__global__ void k_permute(const int* __restrict__ ei, const int* __restrict__ et)
{
    __shared__ int spad[N_REL];
    if (threadIdx.x == 0) {
        int off = 0;
        #pragma unroll
        for (int r = 0; r < N_REL; r++) {
            spad[r] = off;
            off += ((g_hist[r] + 127) & ~127);
        }
    }
    __syncthreads();

    int e = blockIdx.x * blockDim.x + threadIdx.x;
    if (e >= N_EDGES) return;
    int src = __ldg(&ei[e]);
    int dst = __ldg(&ei[N_EDGES + e]);
    int t   = __ldg(&et[e]);
    int lane = threadIdx.x & 31;

    unsigned mask = __match_any_sync(__activemask(), t);
    int leader = __ffs(mask) - 1;
    int rank   = __popc(mask & ((1u << lane) - 1));
    int base = 0;
    if (lane == leader) base = atomicAdd(&g_sortrel[t], __popc(mask));
    base = __shfl_sync(__activemask(), base, leader);
    int pos = spad[t] + base + rank;

    int cnt = g_cnt[t * N_NODES + dst];
    g_s[pos] = src;
    g_d[pos] = dst;
    g_v[pos] = 1.0f / (float)(cnt > 0 ? cnt : 1);
}

// ---------------- fused gather-GEMM-scatter over relation-sorted edges ----------------
template<int NOUT, bool RELU>
__global__ __launch_bounds__(128) void k_fused(const float* __restrict__ X,
                                               const float* __restrict__ Wrel,
                                               float* __restrict__ dest)
{
    constexpr int TO  = NOUT / 4;
    constexpr int NW2 = TO / 2;

    __shared__ float xs[64][128];
    __shared__ float ws[64 * NOUT];
    __shared__ int   ds[128];
    __shared__ float vs[128];
    __shared__ int   spad[N_REL + 1];

    if (threadIdx.x == 0) {
        int off = 0;
        #pragma unroll
        for (int r = 0; r < N_REL; r++) {
            spad[r] = off;
            off += ((g_hist[r] + 127) & ~127);
        }
        spad[N_REL] = off;
    }
    __syncthreads();

    const int b0 = blockIdx.x * 128;
    int r = 0;
    #pragma unroll
    for (int i = 1; i < N_REL; i++)
        if (b0 >= spad[i]) r = i;

    // stage this thread's edge
    {
        int t = threadIdx.x;
        int slot = b0 + t;
        int src = g_s[slot];
        ds[t] = g_d[slot];
        vs[t] = g_v[slot];
        const float* xrow = X + (size_t)src * 64;
        #pragma unroll
        for (int g = 0; g < 16; g++) {
            float4 v = __ldg((const float4*)(xrow + g * 4));
            if (RELU) {
                v.x = fmaxf(v.x, 0.f); v.y = fmaxf(v.y, 0.f);
                v.z = fmaxf(v.z, 0.f); v.w = fmaxf(v.w, 0.f);
            }
            xs[g * 4 + 0][t] = v.x;
            xs[g * 4 + 1][t] = v.y;
            xs[g * 4 + 2][t] = v.z;
            xs[g * 4 + 3][t] = v.w;
        }
    }
    const float* W = Wrel + (size_t)r * 64 * NOUT;
    for (int i = threadIdx.x * 4; i < 64 * NOUT; i += 128 * 4)
        *(float4*)(ws + i) = *(const float4*)(W + i);
    __syncthreads();

    const int lane = threadIdx.x & 31;
    const int og   = threadIdx.x >> 5;
    const int o0   = og * TO;
    const int m0   = lane * 4;

    unsigned long long acc[4][NW2];
    #pragma unroll
    for (int i = 0; i < 4; i++)
        #pragma unroll
        for (int j = 0; j < NW2; j++) acc[i][j] = 0ull;

    #pragma unroll 4
    for (int k = 0; k < 64; k++) {
        float4 xv = *(const float4*)&xs[k][m0];
        unsigned long long x2[4];
        asm("mov.b64 %0, {%1, %1};" : "=l"(x2[0]) : "f"(xv.x));
        asm("mov.b64 %0, {%1, %1};" : "=l"(x2[1]) : "f"(xv.y));
        asm("mov.b64 %0, {%1, %1};" : "=l"(x2[2]) : "f"(xv.z));
        asm("mov.b64 %0, {%1, %1};" : "=l"(x2[3]) : "f"(xv.w));
        unsigned long long w2[NW2];
        #pragma unroll
        for (int q = 0; q < TO / 4; q++) {
            float4 wa = *(const float4*)(ws + k * NOUT + o0 + q * 4);
            asm("mov.b64 %0, {%1, %2};" : "=l"(w2[q * 2 + 0]) : "f"(wa.x), "f"(wa.y));
            asm("mov.b64 %0, {%1, %2};" : "=l"(w2[q * 2 + 1]) : "f"(wa.z), "f"(wa.w));
        }
        #pragma unroll
        for (int j = 0; j < NW2; j++)
            #pragma unroll
            for (int i = 0; i < 4; i++)
                asm("fma.rn.f32x2 %0, %1, %2, %0;" : "+l"(acc[i][j]) : "l"(x2[i]), "l"(w2[j]));
    }

    #pragma unroll
    for (int i = 0; i < 4; i++) {
        int m = m0 + i;
        float inv = vs[m];
        float* op = dest + (size_t)ds[m] * NOUT + o0;
        #pragma unroll
        for (int j = 0; j < NW2; j += 2) {
            float2 a = *(float2*)&acc[i][j];
            float2 b = *(float2*)&acc[i][j + 1];
            asm volatile("red.global.add.v4.f32 [%0], {%1, %2, %3, %4};"
                         :: "l"(op + 2 * j),
                            "f"(a.x * inv), "f"(a.y * inv), "f"(b.x * inv), "f"(b.y * inv)
                         : "memory");
        }
    }
}

// ---------------- dense self-term GEMM: OUT (+)= act(X) @ W ----------------
template<int NOUT, bool RELU, bool ATOMIC>
__global__ __launch_bounds__(128) void k_dense(const float* __restrict__ X,
                                               const float* __restrict__ W,
                                               float* __restrict__ OUT)
{
    constexpr int TO  = NOUT / 4;
    constexpr int NW2 = TO / 2;

    __shared__ float xs[64][128];
    __shared__ float ws[64 * NOUT];

    const int nb = blockIdx.x * 128;

    for (int t = threadIdx.x; t < 128 * 16; t += 128) {
        int m = t & 127;
        int g = t >> 7;
        float4 v = make_float4(0.f, 0.f, 0.f, 0.f);
        int node = nb + m;
        if (node < N_NODES) v = *(const float4*)(X + (size_t)node * 64 + g * 4);
        if (RELU) {
            v.x = fmaxf(v.x, 0.f); v.y = fmaxf(v.y, 0.f);
            v.z = fmaxf(v.z, 0.f); v.w = fmaxf(v.w, 0.f);
        }
        xs[g * 4 + 0][m] = v.x;
        xs[g * 4 + 1][m] = v.y;
        xs[g * 4 + 2][m] = v.z;
        xs[g * 4 + 3][m] = v.w;
    }
    for (int i = threadIdx.x * 4; i < 64 * NOUT; i += 128 * 4)
        *(float4*)(ws + i) = *(const float4*)(W + i);
    __syncthreads();

    const int lane = threadIdx.x & 31;
    const int og   = threadIdx.x >> 5;
    const int o0   = og * TO;
    const int m0   = lane * 4;

    unsigned long long acc[4][NW2];
    #pragma unroll
    for (int i = 0; i < 4; i++)
        #pragma unroll
        for (int j = 0; j < NW2; j++) acc[i][j] = 0ull;

    #pragma unroll 4
    for (int k = 0; k < 64; k++) {
        float4 xv = *(const float4*)&xs[k][m0];
        unsigned long long x2[4];
        asm("mov.b64 %0, {%1, %1};" : "=l"(x2[0]) : "f"(xv.x));
        asm("mov.b64 %0, {%1, %1};" : "=l"(x2[1]) : "f"(xv.y));
        asm("mov.b64 %0, {%1, %1};" : "=l"(x2[2]) : "f"(xv.z));
        asm("mov.b64 %0, {%1, %1};" : "=l"(x2[3]) : "f"(xv.w));
        unsigned long long w2[NW2];
        #pragma unroll
        for (int q = 0; q < TO / 4; q++) {
            float4 wa = *(const float4*)(ws + k * NOUT + o0 + q * 4);
            asm("mov.b64 %0, {%1, %2};" : "=l"(w2[q * 2 + 0]) : "f"(wa.x), "f"(wa.y));
            asm("mov.b64 %0, {%1, %2};" : "=l"(w2[q * 2 + 1]) : "f"(wa.z), "f"(wa.w));
        }
        #pragma unroll
        for (int j = 0; j < NW2; j++)
            #pragma unroll
            for (int i = 0; i < 4; i++)
                asm("fma.rn.f32x2 %0, %1, %2, %0;" : "+l"(acc[i][j]) : "l"(x2[i]), "l"(w2[j]));
    }

    #pragma unroll
    for (int i = 0; i < 4; i++) {
        int m = m0 + i;
        if (nb + m < N_NODES) {
            float* op = OUT + (size_t)(nb + m) * NOUT + o0;
            #pragma unroll
            for (int j = 0; j < NW2; j += 2) {
                float2 a = *(float2*)&acc[i][j];
                float2 b = *(float2*)&acc[i][j + 1];
                if (ATOMIC) {
                    asm volatile("red.global.add.v4.f32 [%0], {%1, %2, %3, %4};"
                                 :: "l"(op + 2 * j), "f"(a.x), "f"(a.y), "f"(b.x), "f"(b.y)
                                 : "memory");
                } else {
                    *(float4*)(op + 2 * j) = make_float4(a.x, a.y, b.x, b.y);
                }
            }
        }
    }
}

// ---------------- launch ----------------
extern "C" void kernel_launch(void* const* d_in, const int* in_sizes, int n_in,
                              void* d_out, int out_size)
{
    const float* x       = (const float*)d_in[0];
    const float* bases1  = (const float*)d_in[1];
    const float* coeffs1 = (const float*)d_in[2];
    const float* self1   = (const float*)d_in[3];
    const float* bases2  = (const float*)d_in[4];
    const float* coeffs2 = (const float*)d_in[5];
    const float* self2   = (const float*)d_in[6];
    const int* ei        = (const int*)d_in[7];
    const int* et        = (const int*)d_in[8];
    float* out = (float*)d_out;

    const int NODE_TILES = (N_NODES + 127) / 128;   // 391

    float* w1p; cudaGetSymbolAddress((void**)&w1p, g_W1);
    float* w2p; cudaGetSymbolAddress((void**)&w2p, g_W2);
    float* hp;  cudaGetSymbolAddress((void**)&hp,  g_h);

    // launch #1: weights + zero everything (h zeroed here; layer-1 accumulates atomically)
    k_init<<<1024, 256>>>(bases1, coeffs1, bases2, coeffs2);
    // #2: per-(rel,dst) counts + per-rel histogram
    k_counthist<<<(N_EDGES + 255) / 256, 256>>>(ei, et);
    // #3: counting-sort edges by relation
    k_permute<<<(N_EDGES + 255) / 256, 256>>>(ei, et);
    // #4 (profiled): layer-1 fused edge GEMM -> atomic into h
    k_fused<D_HID, false><<<NBLK_E, 128>>>(x, w1p, hp);
    // #5: h += x @ self1 (atomic)
    k_dense<D_HID, false, true><<<NODE_TILES, 128>>>(x, self1, hp);
    // #6: out = relu(h) @ self2 (plain store, covers whole out buffer)
    k_dense<N_CLASS, true, false><<<NODE_TILES, 128>>>(hp, self2, out);
    // #7: layer-2 fused edge GEMM -> atomic into out
    k_fused<N_CLASS, true><<<NBLK_E, 128>>>(hp, w2p, out);
}

// round 8
// speedup vs baseline: 1.3730x; 1.1211x over previous
#include <cuda_runtime.h>
#include <cstdint>

#define N_NODES 50000
#define N_REL   16
#define N_BASIS 8
#define D_IN    64
#define D_HID   64
#define N_CLASS 16
#define N_EDGES 800000

// padded sorted-edge capacity: 16 bins each padded to multiple of 128
#define ES      802176              // 6267 * 128
#define NBLK_E  6267

// ---------------- device scratch ----------------
__device__ __align__(16) float g_W1[N_REL * D_IN * D_HID];      // 256 KB
__device__ __align__(16) float g_W2[N_REL * D_HID * N_CLASS];   // 64 KB
__device__ __align__(16) float g_h [N_NODES * D_HID];           // 12.8 MB
__device__ __align__(16) int   g_cnt[N_REL * N_NODES];          // 3.2 MB
__device__ int   g_hist[N_REL];
__device__ int   g_sortrel[N_REL];
__device__ __align__(16) int   g_s[ES];
__device__ __align__(16) int   g_d[ES];
__device__ __align__(16) float g_v[ES];

// ---------------- init: weights + zero all mutable state ----------------
__global__ void k_init(const float* __restrict__ bases1, const float* __restrict__ coeffs1,
                       const float* __restrict__ bases2, const float* __restrict__ coeffs2)
{
    int bid = blockIdx.x;
    if (bid < 16) {
        int r = bid;
        float c[N_BASIS];
        #pragma unroll
        for (int b = 0; b < N_BASIS; b++) c[b] = coeffs1[r * N_BASIS + b];
        for (int i = threadIdx.x; i < D_IN * D_HID; i += blockDim.x) {
            float s = 0.f;
            #pragma unroll
            for (int b = 0; b < N_BASIS; b++) s += c[b] * bases1[b * D_IN * D_HID + i];
            g_W1[r * D_IN * D_HID + i] = s;
        }
    } else if (bid < 32) {
        int r = bid - 16;
        float c[N_BASIS];
        #pragma unroll
        for (int b = 0; b < N_BASIS; b++) c[b] = coeffs2[r * N_BASIS + b];
        for (int i = threadIdx.x; i < D_HID * N_CLASS; i += blockDim.x) {
            float s = 0.f;
            #pragma unroll
            for (int b = 0; b < N_BASIS; b++) s += c[b] * bases2[b * D_HID * N_CLASS + i];
            g_W2[r * D_HID * N_CLASS + i] = s;
        }
    }
    int nthreads = gridDim.x * blockDim.x;
    int gt = bid * blockDim.x + threadIdx.x;
    for (int i = gt; i < N_REL * N_NODES; i += nthreads) g_cnt[i] = 0;
    for (int i = gt; i < ES; i += nthreads) { g_s[i] = 0; g_d[i] = 0; g_v[i] = 0.f; }
    for (int i = gt; i < N_NODES * D_HID / 4; i += nthreads)
        ((float4*)g_h)[i] = make_float4(0.f, 0.f, 0.f, 0.f);
    if (gt < N_REL) { g_hist[gt] = 0; g_sortrel[gt] = 0; }
}

// ---------------- count per-(rel,dst) + per-rel histogram ----------------
__global__ void k_counthist(const int* __restrict__ ei, const int* __restrict__ et)
{
    __shared__ int lh[N_REL];
    if (threadIdx.x < N_REL) lh[threadIdx.x] = 0;
    __syncthreads();
    int e = blockIdx.x * blockDim.x + threadIdx.x;
    if (e < N_EDGES) {
        int dst = __ldg(&ei[N_EDGES + e]);
        int t   = __ldg(&et[e]);
        atomicAdd(&g_cnt[t * N_NODES + dst], 1);
        atomicAdd(&lh[t], 1);
    }
    __syncthreads();
    if (threadIdx.x < N_REL && lh[threadIdx.x] > 0)
        atomicAdd(&g_hist[threadIdx.x], lh[threadIdx.x]);
}

// ---------------- counting-sort permute (inline scan) + inv ----------------
__global__ void k_permute(const int* __restrict__ ei, const int* __restrict__ et)
{
    __shared__ int spad[N_REL];
    if (threadIdx.x == 0) {
        int off = 0;
        #pragma unroll
        for (int r = 0; r < N_REL; r++) {
            spad[r] = off;
            off += ((g_hist[r] + 127) & ~127);
        }
    }
    __syncthreads();

    int e = blockIdx.x * blockDim.x + threadIdx.x;
    if (e >= N_EDGES) return;
    int src = __ldg(&ei[e]);
    int dst = __ldg(&ei[N_EDGES + e]);
    int t   = __ldg(&et[e]);
    int lane = threadIdx.x & 31;

    unsigned mask = __match_any_sync(__activemask(), t);
    int leader = __ffs(mask) - 1;
    int rank   = __popc(mask & ((1u << lane) - 1));
    int base = 0;
    if (lane == leader) base = atomicAdd(&g_sortrel[t], __popc(mask));
    base = __shfl_sync(__activemask(), base, leader);
    int pos = spad[t] + base + rank;

    int cnt = g_cnt[t * N_NODES + dst];
    g_s[pos] = src;
    g_d[pos] = dst;
    g_v[pos] = 1.0f / (float)(cnt > 0 ? cnt : 1);
}

// ---------------- unified 128-row tile GEMM ----------------
// FUSED: rows are relation-sorted edges; msg = X[g_s] @ W_r; dest[g_d] += g_v * msg
// !FUSED: rows are nodes b0+m; dest[node] (+)= act(X[node]) @ W
// smem x tile is k-major with XOR swizzle: phys col = m ^ (k & 28)  (k&28 toggles
// bits 2..4 only -> float4 reads stay aligned; coalesced staging STS is ~2-way).
template<int NOUT, bool RELU, bool FUSED, bool ATOMIC>
__global__ __launch_bounds__(128) void k_tile(const float* __restrict__ X,
                                              const float* __restrict__ Wbase,
                                              float* __restrict__ dest)
{
    constexpr int TO  = NOUT / 4;
    constexpr int NW2 = TO / 2;

    __shared__ float xs[64][128];
    __shared__ float ws[64 * NOUT];
    __shared__ int   ssrc[128];
    __shared__ int   ds[128];
    __shared__ float vs[128];
    __shared__ int   spad[N_REL];

    const int tid  = threadIdx.x;
    const int lane = tid & 31;
    const int og   = tid >> 5;
    const int b0   = blockIdx.x * 128;

    const float* W;
    if (FUSED) {
        if (tid == 0) {
            int off = 0;
            #pragma unroll
            for (int r = 0; r < N_REL; r++) {
                spad[r] = off;
                off += ((g_hist[r] + 127) & ~127);
            }
        }
        ssrc[tid] = g_s[b0 + tid];
        ds[tid]   = g_d[b0 + tid];
        vs[tid]   = g_v[b0 + tid];
        __syncthreads();
        int r = 0;
        #pragma unroll
        for (int i = 1; i < N_REL; i++)
            if (b0 >= spad[i]) r = i;
        W = Wbase + (size_t)r * 64 * NOUT;
    } else {
        ssrc[tid] = b0 + tid;
        __syncwarp();
        W = Wbase;
    }

    // coalesced staging: per iter, warp loads 2 full rows (16 lanes x 16B each)
    {
        #pragma unroll
        for (int i = 0; i < 16; i++) {
            int row = og * 32 + i * 2 + (lane >> 4);
            int g   = lane & 15;
            int src = ssrc[row];
            float4 v = make_float4(0.f, 0.f, 0.f, 0.f);
            bool valid = FUSED ? true : (src < N_NODES);
            if (valid) v = __ldg((const float4*)(X + (size_t)src * 64 + g * 4));
            if (RELU) {
                v.x = fmaxf(v.x, 0.f); v.y = fmaxf(v.y, 0.f);
                v.z = fmaxf(v.z, 0.f); v.w = fmaxf(v.w, 0.f);
            }
            int mp = row ^ ((g & 7) << 2);      // = row ^ ((4g)&28)
            xs[4 * g + 0][mp] = v.x;
            xs[4 * g + 1][mp] = v.y;
            xs[4 * g + 2][mp] = v.z;
            xs[4 * g + 3][mp] = v.w;
        }
    }
    for (int i = tid * 4; i < 64 * NOUT; i += 128 * 4)
        *(float4*)(ws + i) = *(const float4*)(W + i);
    __syncthreads();

    const int o0 = og * TO;
    const int m0 = lane * 4;

    unsigned long long acc[4][NW2];
    #pragma unroll
    for (int i = 0; i < 4; i++)
        #pragma unroll
        for (int j = 0; j < NW2; j++) acc[i][j] = 0ull;

    #pragma unroll 8
    for (int k = 0; k < 64; k++) {
        float4 xv = *(const float4*)&xs[k][m0 ^ (k & 28)];
        unsigned long long x2[4];
        asm("mov.b64 %0, {%1, %1};" : "=l"(x2[0]) : "f"(xv.x));
        asm("mov.b64 %0, {%1, %1};" : "=l"(x2[1]) : "f"(xv.y));
        asm("mov.b64 %0, {%1, %1};" : "=l"(x2[2]) : "f"(xv.z));
        asm("mov.b64 %0, {%1, %1};" : "=l"(x2[3]) : "f"(xv.w));
        unsigned long long w2[NW2];
        #pragma unroll
        for (int q = 0; q < TO / 4; q++) {
            float4 wa = *(const float4*)(ws + k * NOUT + o0 + q * 4);
            asm("mov.b64 %0, {%1, %2};" : "=l"(w2[q * 2 + 0]) : "f"(wa.x), "f"(wa.y));
            asm("mov.b64 %0, {%1, %2};" : "=l"(w2[q * 2 + 1]) : "f"(wa.z), "f"(wa.w));
        }
        #pragma unroll
        for (int j = 0; j < NW2; j++)
            #pragma unroll
            for (int i = 0; i < 4; i++)
                asm("fma.rn.f32x2 %0, %1, %2, %0;" : "+l"(acc[i][j]) : "l"(x2[i]), "l"(w2[j]));
    }

    // epilogue (swizzle only permutes which lane holds which m within a 32-row
    // group; each thread's logical rows are still m0..m0+3)
    #pragma unroll
    for (int i = 0; i < 4; i++) {
        int m = m0 + i;
        if (FUSED) {
            float inv = vs[m];
            float* op = dest + (size_t)ds[m] * NOUT + o0;
            #pragma unroll
            for (int j = 0; j < NW2; j += 2) {
                float2 a = *(float2*)&acc[i][j];
                float2 b = *(float2*)&acc[i][j + 1];
                asm volatile("red.global.add.v4.f32 [%0], {%1, %2, %3, %4};"
                             :: "l"(op + 2 * j),
                                "f"(a.x * inv), "f"(a.y * inv), "f"(b.x * inv), "f"(b.y * inv)
                             : "memory");
            }
        } else {
            int node = b0 + m;
            if (node < N_NODES) {
                float* op = dest + (size_t)node * NOUT + o0;
                #pragma unroll
                for (int j = 0; j < NW2; j += 2) {
                    float2 a = *(float2*)&acc[i][j];
                    float2 b = *(float2*)&acc[i][j + 1];
                    if (ATOMIC) {
                        asm volatile("red.global.add.v4.f32 [%0], {%1, %2, %3, %4};"
                                     :: "l"(op + 2 * j), "f"(a.x), "f"(a.y), "f"(b.x), "f"(b.y)
                                     : "memory");
                    } else {
                        *(float4*)(op + 2 * j) = make_float4(a.x, a.y, b.x, b.y);
                    }
                }
            }
        }
    }
}

// ---------------- launch ----------------
extern "C" void kernel_launch(void* const* d_in, const int* in_sizes, int n_in,
                              void* d_out, int out_size)
{
    const float* x       = (const float*)d_in[0];
    const float* bases1  = (const float*)d_in[1];
    const float* coeffs1 = (const float*)d_in[2];
    const float* self1   = (const float*)d_in[3];
    const float* bases2  = (const float*)d_in[4];
    const float* coeffs2 = (const float*)d_in[5];
    const float* self2   = (const float*)d_in[6];
    const int* ei        = (const int*)d_in[7];
    const int* et        = (const int*)d_in[8];
    float* out = (float*)d_out;

    const int NODE_TILES = (N_NODES + 127) / 128;   // 391

    float* w1p; cudaGetSymbolAddress((void**)&w1p, g_W1);
    float* w2p; cudaGetSymbolAddress((void**)&w2p, g_W2);
    float* hp;  cudaGetSymbolAddress((void**)&hp,  g_h);

    // #1 weights + zero everything
    k_init<<<1024, 256>>>(bases1, coeffs1, bases2, coeffs2);
    // #2 counts + histogram
    k_counthist<<<(N_EDGES + 255) / 256, 256>>>(ei, et);
    // #3 counting-sort by relation
    k_permute<<<(N_EDGES + 255) / 256, 256>>>(ei, et);
    // #4 (profiled): layer-1 fused edge GEMM -> atomic into h
    k_tile<D_HID, false, true, true><<<NBLK_E, 128>>>(x, w1p, hp);
    // #5 h += x @ self1 (atomic)
    k_tile<D_HID, false, false, true><<<NODE_TILES, 128>>>(x, self1, hp);
    // #6 out = relu(h) @ self2 (plain store)
    k_tile<N_CLASS, true, false, false><<<NODE_TILES, 128>>>(hp, self2, out);
    // #7 layer-2 fused edge GEMM -> atomic into out
    k_tile<N_CLASS, true, true, true><<<NBLK_E, 128>>>(hp, w2p, out);
}

// round 10
// speedup vs baseline: 1.9232x; 1.4008x over previous
#include <cuda_runtime.h>
#include <cuda_bf16.h>
#include <cstdint>

#define N_NODES 50000
#define N_REL   16
#define N_BASIS 8
#define D_IN    64
#define D_HID   64
#define N_CLASS 16
#define N_EDGES 800000

#define ES      802176              // 6267 * 128 (16 bins padded to 128)
#define NBLK_E  6267

// ---------------- device scratch ----------------
// B fragments for mma.sync m16n8k16 row.col, PTX-lane layout:
// idx = ((((rel*2 + hl)*4 + ks)*NT + nt)*32 + lane)*2 + j
__device__ __align__(16) uint32_t g_W1f[N_REL * 2 * 4 * 8 * 32 * 2];   // 128 KB
__device__ __align__(16) uint32_t g_W2f[N_REL * 2 * 4 * 2 * 32 * 2];   // 32 KB
__device__ __align__(16) __nv_bfloat16 g_Xh[N_NODES * 64];
__device__ __align__(16) __nv_bfloat16 g_Xl[N_NODES * 64];
__device__ __align__(16) __nv_bfloat16 g_Hh[N_NODES * 64];
__device__ __align__(16) __nv_bfloat16 g_Hl[N_NODES * 64];
__device__ __align__(16) float g_h [N_NODES * D_HID];
__device__ __align__(16) int   g_cnt[N_REL * N_NODES];
__device__ int   g_hist[N_REL];
__device__ int   g_sortrel[N_REL];
__device__ __align__(16) int   g_s[ES];
__device__ __align__(16) int   g_d[ES];
__device__ __align__(16) float g_v[ES];

// ---------------- helpers ----------------
__device__ __forceinline__ uint32_t sw128(uint32_t o) { return o ^ ((o >> 3) & 0x70); }
__device__ __forceinline__ uint32_t smem_u32(const void* p) {
    uint32_t a;
    asm("{ .reg .u64 t; cvta.to.shared.u64 t, %1; cvt.u32.u64 %0, t; }" : "=r"(a) : "l"(p));
    return a;
}
__device__ __forceinline__ void red_v4(float* p, float a, float b, float c, float d) {
    asm volatile("red.global.add.v4.f32 [%0], {%1, %2, %3, %4};"
                 :: "l"(p), "f"(a), "f"(b), "f"(c), "f"(d) : "memory");
}
__device__ __forceinline__ void red_v2(float* p, float a, float b) {
    asm volatile("red.global.add.v2.f32 [%0], {%1, %2};"
                 :: "l"(p), "f"(a), "f"(b) : "memory");
}
__device__ __forceinline__ void bf16_split(float v, __nv_bfloat16& hi, __nv_bfloat16& lo) {
    hi = __float2bfloat16(v);
    lo = __float2bfloat16(v - __bfloat162float(hi));
}
__device__ __forceinline__ void ldm_x4(uint32_t& a0, uint32_t& a1, uint32_t& a2, uint32_t& a3,
                                       uint32_t addr) {
    asm volatile("ldmatrix.sync.aligned.m8n8.x4.shared.b16 {%0,%1,%2,%3}, [%4];"
                 : "=r"(a0), "=r"(a1), "=r"(a2), "=r"(a3) : "r"(addr));
}
__device__ __forceinline__ void mma_bf16(float& c0, float& c1, float& c2, float& c3,
                                         uint32_t a0, uint32_t a1, uint32_t a2, uint32_t a3,
                                         uint32_t b0, uint32_t b1) {
    asm volatile("mma.sync.aligned.m16n8k16.row.col.f32.bf16.bf16.f32 "
                 "{%0,%1,%2,%3}, {%4,%5,%6,%7}, {%8,%9}, {%0,%1,%2,%3};"
                 : "+f"(c0), "+f"(c1), "+f"(c2), "+f"(c3)
                 : "r"(a0), "r"(a1), "r"(a2), "r"(a3), "r"(b0), "r"(b1));
}

// ---------------- init: W frags (split, lane layout), X split, zero state ----------------
__global__ void k_init(const float* __restrict__ bases1, const float* __restrict__ coeffs1,
                       const float* __restrict__ bases2, const float* __restrict__ coeffs2,
                       const float* __restrict__ x)
{
    int nthreads = gridDim.x * blockDim.x;
    int gt = blockIdx.x * blockDim.x + threadIdx.x;

    // layer-1 B fragments: NT=8, NOUT=64
    for (int idx = gt; idx < N_REL * 2 * 4 * 8 * 32 * 2; idx += nthreads) {
        int j    = idx & 1;
        int lane = (idx >> 1) & 31;
        int nt   = (idx >> 6) & 7;
        int ks   = (idx >> 9) & 3;
        int hl   = (idx >> 11) & 1;
        int rel  = idx >> 12;
        int n  = nt * 8 + (lane >> 2);
        int k0 = ks * 16 + (lane & 3) * 2 + j * 8;
        float w0 = 0.f, w1 = 0.f;
        #pragma unroll
        for (int b = 0; b < N_BASIS; b++) {
            float c = coeffs1[rel * N_BASIS + b];
            w0 += c * bases1[b * 4096 + k0 * 64 + n];
            w1 += c * bases1[b * 4096 + (k0 + 1) * 64 + n];
        }
        __nv_bfloat16 h0, l0, h1, l1;
        bf16_split(w0, h0, l0); bf16_split(w1, h1, l1);
        uint16_t u0 = hl ? __bfloat16_as_ushort(l0) : __bfloat16_as_ushort(h0);
        uint16_t u1 = hl ? __bfloat16_as_ushort(l1) : __bfloat16_as_ushort(h1);
        g_W1f[idx] = (uint32_t)u0 | ((uint32_t)u1 << 16);
    }
    // layer-2 B fragments: NT=2, NOUT=16
    for (int idx = gt; idx < N_REL * 2 * 4 * 2 * 32 * 2; idx += nthreads) {
        int j    = idx & 1;
        int lane = (idx >> 1) & 31;
        int nt   = (idx >> 6) & 1;
        int ks   = (idx >> 7) & 3;
        int hl   = (idx >> 9) & 1;
        int rel  = idx >> 10;
        int n  = nt * 8 + (lane >> 2);
        int k0 = ks * 16 + (lane & 3) * 2 + j * 8;
        float w0 = 0.f, w1 = 0.f;
        #pragma unroll
        for (int b = 0; b < N_BASIS; b++) {
            float c = coeffs2[rel * N_BASIS + b];
            w0 += c * bases2[b * 1024 + k0 * 16 + n];
            w1 += c * bases2[b * 1024 + (k0 + 1) * 16 + n];
        }
        __nv_bfloat16 h0, l0, h1, l1;
        bf16_split(w0, h0, l0); bf16_split(w1, h1, l1);
        uint16_t u0 = hl ? __bfloat16_as_ushort(l0) : __bfloat16_as_ushort(h0);
        uint16_t u1 = hl ? __bfloat16_as_ushort(l1) : __bfloat16_as_ushort(h1);
        g_W2f[idx] = (uint32_t)u0 | ((uint32_t)u1 << 16);
    }
    for (int j = gt; j < N_NODES * 64; j += nthreads) {
        __nv_bfloat16 hi, lo; bf16_split(x[j], hi, lo);
        g_Xh[j] = hi; g_Xl[j] = lo;
    }
    for (int i = gt; i < N_REL * N_NODES; i += nthreads) g_cnt[i] = 0;
    for (int i = gt; i < ES; i += nthreads) { g_s[i] = 0; g_d[i] = 0; g_v[i] = 0.f; }
    for (int i = gt; i < N_NODES * D_HID / 4; i += nthreads)
        ((float4*)g_h)[i] = make_float4(0.f, 0.f, 0.f, 0.f);
    if (gt < N_REL) { g_hist[gt] = 0; g_sortrel[gt] = 0; }
}

// ---------------- count + histogram ----------------
__global__ void k_counthist(const int* __restrict__ ei, const int* __restrict__ et)
{
    __shared__ int lh[N_REL];
    if (threadIdx.x < N_REL) lh[threadIdx.x] = 0;
    __syncthreads();
    int e = blockIdx.x * blockDim.x + threadIdx.x;
    if (e < N_EDGES) {
        int dst = __ldg(&ei[N_EDGES + e]);
        int t   = __ldg(&et[e]);
        atomicAdd(&g_cnt[t * N_NODES + dst], 1);
        atomicAdd(&lh[t], 1);
    }
    __syncthreads();
    if (threadIdx.x < N_REL && lh[threadIdx.x] > 0)
        atomicAdd(&g_hist[threadIdx.x], lh[threadIdx.x]);
}

// ---------------- counting-sort permute + inv ----------------
__global__ void k_permute(const int* __restrict__ ei, const int* __restrict__ et)
{
    __shared__ int spad[N_REL];
    if (threadIdx.x == 0) {
        int off = 0;
        #pragma unroll
        for (int r = 0; r < N_REL; r++) { spad[r] = off; off += ((g_hist[r] + 127) & ~127); }
    }
    __syncthreads();

    int e = blockIdx.x * blockDim.x + threadIdx.x;
    if (e >= N_EDGES) return;
    int src = __ldg(&ei[e]);
    int dst = __ldg(&ei[N_EDGES + e]);
    int t   = __ldg(&et[e]);
    int lane = threadIdx.x & 31;

    unsigned mask = __match_any_sync(__activemask(), t);
    int leader = __ffs(mask) - 1;
    int rank   = __popc(mask & ((1u << lane) - 1));
    int base = 0;
    if (lane == leader) base = atomicAdd(&g_sortrel[t], __popc(mask));
    base = __shfl_sync(__activemask(), base, leader);
    int pos = spad[t] + base + rank;

    int cnt = g_cnt[t * N_NODES + dst];
    g_s[pos] = src;
    g_d[pos] = dst;
    g_v[pos] = 1.0f / (float)(cnt > 0 ? cnt : 1);
}

// ---------------- split relu(h) into bf16 hi/lo ----------------
__global__ void k_splith()
{
    int j = blockIdx.x * blockDim.x + threadIdx.x;
    if (j >= N_NODES * 64) return;
    float v = fmaxf(g_h[j], 0.f);
    __nv_bfloat16 hi, lo; bf16_split(v, hi, lo);
    g_Hh[j] = hi; g_Hl[j] = lo;
}

// ---------------- HMMA fused edge GEMM: dest[dst] += inv * (X[src] @ W_rel) ----------------
// 128 edges/block, 4 warps; warp owns 32 edges (2 m16 tiles). 3-pass bf16 split.
template<int NOUT>
__global__ __launch_bounds__(128) void k_hmma(const __nv_bfloat16* __restrict__ Xh,
                                              const __nv_bfloat16* __restrict__ Xl,
                                              const uint32_t* __restrict__ Wf,
                                              float* __restrict__ dest)
{
    constexpr int NT = NOUT / 8;                    // n-tiles (8 or 2)
    constexpr int WFREL = 2 * 4 * NT * 32 * 2;      // u32 per relation

    extern __shared__ __align__(128) char dsm[];
    // layout: Ah [128 rows x 128B] @0, Al @16384, Bfrag @32768
    uint32_t* bfs = (uint32_t*)(dsm + 32768);

    __shared__ int   ssrc[128];
    __shared__ int   ds[128];
    __shared__ float vs[128];
    __shared__ int   spad[N_REL];

    const int tid = threadIdx.x, lane = tid & 31, wid = tid >> 5;
    const int b0 = blockIdx.x * 128;

    if (tid == 0) {
        int off = 0;
        #pragma unroll
        for (int r = 0; r < N_REL; r++) { spad[r] = off; off += ((g_hist[r] + 127) & ~127); }
    }
    ssrc[tid] = g_s[b0 + tid];
    ds[tid]   = g_d[b0 + tid];
    vs[tid]   = g_v[b0 + tid];
    __syncthreads();

    int rel = 0;
    #pragma unroll
    for (int i = 1; i < N_REL; i++)
        if (b0 >= spad[i]) rel = i;

    // stage A hi/lo: warp loads 4 rows/iter (8 lanes x 16B per 128B row), swizzled
    #pragma unroll
    for (int i = 0; i < 8; i++) {
        int row = wid * 32 + i * 4 + (lane >> 3);
        int c   = (lane & 7) * 16;
        int src = ssrc[row];
        uint4 vh = *(const uint4*)((const char*)Xh + (size_t)src * 128 + c);
        uint4 vl = *(const uint4*)((const char*)Xl + (size_t)src * 128 + c);
        uint32_t sw = sw128((uint32_t)(row * 128 + c));
        *(uint4*)(dsm + sw)         = vh;
        *(uint4*)(dsm + 16384 + sw) = vl;
    }
    // copy this relation's B fragments
    {
        const uint32_t* wsrc = Wf + (size_t)rel * WFREL;
        for (int i = tid * 4; i < WFREL; i += 128 * 4)
            *(uint4*)(bfs + i) = *(const uint4*)(wsrc + i);
    }
    __syncthreads();

    const uint32_t a_base = smem_u32(dsm);

    float acc[2][NT][4];
    #pragma unroll
    for (int mt = 0; mt < 2; mt++)
        #pragma unroll
        for (int nt = 0; nt < NT; nt++)
            #pragma unroll
            for (int j = 0; j < 4; j++) acc[mt][nt][j] = 0.f;

    // ldmatrix lane address pieces: row-in-16 = lane&15, k-half = lane>>4
    const int lrow = lane & 15;
    const int lkh  = lane >> 4;

    #pragma unroll
    for (int ks = 0; ks < 4; ks++) {
        // B fragments for this k-step: [hl][nt][2]
        uint32_t bh[NT][2], bl[NT][2];
        #pragma unroll
        for (int nt = 0; nt < NT; nt++) {
            const uint32_t* ph = bfs + (((0 * 4 + ks) * NT + nt) * 32 + lane) * 2;
            const uint32_t* pl = bfs + (((1 * 4 + ks) * NT + nt) * 32 + lane) * 2;
            bh[nt][0] = ph[0]; bh[nt][1] = ph[1];
            bl[nt][0] = pl[0]; bl[nt][1] = pl[1];
        }
        #pragma unroll
        for (int mt = 0; mt < 2; mt++) {
            int row = wid * 32 + mt * 16 + lrow;
            int c   = ks * 2 + lkh;
            uint32_t off = (uint32_t)(row * 128) + (uint32_t)((c ^ (row & 7)) << 4);
            uint32_t ah0, ah1, ah2, ah3, al0, al1, al2, al3;
            ldm_x4(ah0, ah1, ah2, ah3, a_base + off);
            ldm_x4(al0, al1, al2, al3, a_base + 16384 + off);
            #pragma unroll
            for (int nt = 0; nt < NT; nt++) {
                mma_bf16(acc[mt][nt][0], acc[mt][nt][1], acc[mt][nt][2], acc[mt][nt][3],
                         ah0, ah1, ah2, ah3, bh[nt][0], bh[nt][1]);
                mma_bf16(acc[mt][nt][0], acc[mt][nt][1], acc[mt][nt][2], acc[mt][nt][3],
                         ah0, ah1, ah2, ah3, bl[nt][0], bl[nt][1]);
                mma_bf16(acc[mt][nt][0], acc[mt][nt][1], acc[mt][nt][2], acc[mt][nt][3],
                         al0, al1, al2, al3, bh[nt][0], bh[nt][1]);
            }
        }
    }

    // epilogue: C frag rows lane/4 (+8), cols (lane%4)*2 (+1) -> red.v2 scatter
    const int crow = lane >> 2;
    const int ccol = (lane & 3) * 2;
    #pragma unroll
    for (int mt = 0; mt < 2; mt++) {
        int r0 = wid * 32 + mt * 16 + crow;
        int r1 = r0 + 8;
        float i0 = vs[r0], i1 = vs[r1];
        float* p0 = dest + (size_t)ds[r0] * NOUT + ccol;
        float* p1 = dest + (size_t)ds[r1] * NOUT + ccol;
        #pragma unroll
        for (int nt = 0; nt < NT; nt++) {
            red_v2(p0 + nt * 8, acc[mt][nt][0] * i0, acc[mt][nt][1] * i0);
            red_v2(p1 + nt * 8, acc[mt][nt][2] * i1, acc[mt][nt][3] * i1);
        }
    }
}

// ---------------- dense self-term GEMM (exact f32): OUT (+)= act(X) @ W ----------------
template<int NOUT, bool RELU, bool ATOMIC>
__global__ __launch_bounds__(128) void k_dense(const float* __restrict__ X,
                                               const float* __restrict__ W,
                                               float* __restrict__ OUT)
{
    constexpr int TO  = NOUT / 4;
    constexpr int NW2 = TO / 2;

    __shared__ float xs[64][128];
    __shared__ float ws[64 * NOUT];

    const int tid  = threadIdx.x;
    const int lane = tid & 31;
    const int og   = tid >> 5;
    const int b0   = blockIdx.x * 128;

    #pragma unroll
    for (int i = 0; i < 16; i++) {
        int row = og * 32 + i * 2 + (lane >> 4);
        int g   = lane & 15;
        int node = b0 + row;
        float4 v = make_float4(0.f, 0.f, 0.f, 0.f);
        if (node < N_NODES) v = __ldg((const float4*)(X + (size_t)node * 64 + g * 4));
        if (RELU) {
            v.x = fmaxf(v.x, 0.f); v.y = fmaxf(v.y, 0.f);
            v.z = fmaxf(v.z, 0.f); v.w = fmaxf(v.w, 0.f);
        }
        int mp = row ^ ((g & 7) << 2);
        xs[4 * g + 0][mp] = v.x;
        xs[4 * g + 1][mp] = v.y;
        xs[4 * g + 2][mp] = v.z;
        xs[4 * g + 3][mp] = v.w;
    }
    for (int i = tid * 4; i < 64 * NOUT; i += 128 * 4)
        *(float4*)(ws + i) = *(const float4*)(W + i);
    __syncthreads();

    const int o0 = og * TO;
    const int m0 = lane * 4;

    unsigned long long acc[4][NW2];
    #pragma unroll
    for (int i = 0; i < 4; i++)
        #pragma unroll
        for (int j = 0; j < NW2; j++) acc[i][j] = 0ull;

    #pragma unroll 8
    for (int k = 0; k < 64; k++) {
        float4 xv = *(const float4*)&xs[k][m0 ^ (k & 28)];
        unsigned long long x2[4];
        asm("mov.b64 %0, {%1, %1};" : "=l"(x2[0]) : "f"(xv.x));
        asm("mov.b64 %0, {%1, %1};" : "=l"(x2[1]) : "f"(xv.y));
        asm("mov.b64 %0, {%1, %1};" : "=l"(x2[2]) : "f"(xv.z));
        asm("mov.b64 %0, {%1, %1};" : "=l"(x2[3]) : "f"(xv.w));
        unsigned long long w2[NW2];
        #pragma unroll
        for (int q = 0; q < TO / 4; q++) {
            float4 wa = *(const float4*)(ws + k * NOUT + o0 + q * 4);
            asm("mov.b64 %0, {%1, %2};" : "=l"(w2[q * 2 + 0]) : "f"(wa.x), "f"(wa.y));
            asm("mov.b64 %0, {%1, %2};" : "=l"(w2[q * 2 + 1]) : "f"(wa.z), "f"(wa.w));
        }
        #pragma unroll
        for (int j = 0; j < NW2; j++)
            #pragma unroll
            for (int i = 0; i < 4; i++)
                asm("fma.rn.f32x2 %0, %1, %2, %0;" : "+l"(acc[i][j]) : "l"(x2[i]), "l"(w2[j]));
    }

    #pragma unroll
    for (int i = 0; i < 4; i++) {
        int node = b0 + m0 + i;
        if (node < N_NODES) {
            float* op = OUT + (size_t)node * NOUT + o0;
            #pragma unroll
            for (int j = 0; j < NW2; j += 2) {
                float2 a = *(float2*)&acc[i][j];
                float2 b = *(float2*)&acc[i][j + 1];
                if (ATOMIC) red_v4(op + 2 * j, a.x, a.y, b.x, b.y);
                else *(float4*)(op + 2 * j) = make_float4(a.x, a.y, b.x, b.y);
            }
        }
    }
}

// ---------------- launch ----------------
extern "C" void kernel_launch(void* const* d_in, const int* in_sizes, int n_in,
                              void* d_out, int out_size)
{
    const float* x       = (const float*)d_in[0];
    const float* bases1  = (const float*)d_in[1];
    const float* coeffs1 = (const float*)d_in[2];
    const float* self1   = (const float*)d_in[3];
    const float* bases2  = (const float*)d_in[4];
    const float* coeffs2 = (const float*)d_in[5];
    const float* self2   = (const float*)d_in[6];
    const int* ei        = (const int*)d_in[7];
    const int* et        = (const int*)d_in[8];
    float* out = (float*)d_out;

    const int NODE_TILES = (N_NODES + 127) / 128;   // 391
    const int DSM1 = 32768 + N_REL * 0 + 2 * 4 * 8 * 32 * 2 * 4;   // 32768 + 16384 = 49152
    const int DSM2 = 32768 + 2 * 4 * 2 * 32 * 2 * 4;               // 32768 + 4096  = 36864

    float* hp;  cudaGetSymbolAddress((void**)&hp,  g_h);
    uint32_t *w1f, *w2f;
    cudaGetSymbolAddress((void**)&w1f, g_W1f);
    cudaGetSymbolAddress((void**)&w2f, g_W2f);
    __nv_bfloat16 *xh, *xl, *hh, *hl;
    cudaGetSymbolAddress((void**)&xh, g_Xh);
    cudaGetSymbolAddress((void**)&xl, g_Xl);
    cudaGetSymbolAddress((void**)&hh, g_Hh);
    cudaGetSymbolAddress((void**)&hl, g_Hl);

    cudaFuncSetAttribute(k_hmma<D_HID>,   cudaFuncAttributeMaxDynamicSharedMemorySize, DSM1);
    cudaFuncSetAttribute(k_hmma<N_CLASS>, cudaFuncAttributeMaxDynamicSharedMemorySize, DSM2);

    // #1 W fragments (split, mma lane layout) + X split + zero state
    k_init<<<1024, 256>>>(bases1, coeffs1, bases2, coeffs2, x);
    // #2 counts + histogram
    k_counthist<<<(N_EDGES + 255) / 256, 256>>>(ei, et);
    // #3 counting-sort by relation
    k_permute<<<(N_EDGES + 255) / 256, 256>>>(ei, et);
    // #4 (profiled): layer-1 fused HMMA edge GEMM -> atomic into h
    k_hmma<D_HID><<<NBLK_E, 128, DSM1>>>(xh, xl, w1f, hp);
    // #5 h += x @ self1 (exact f32, atomic)
    k_dense<D_HID, false, true><<<NODE_TILES, 128>>>(x, self1, hp);
    // #6 relu + bf16-split h
    k_splith<<<(N_NODES * 64 + 255) / 256, 256>>>();
    // #7 out = relu(h) @ self2 (plain store covers out)
    k_dense<N_CLASS, true, false><<<NODE_TILES, 128>>>(hp, self2, out);
    // #8 layer-2 fused HMMA edge GEMM -> atomic into out
    k_hmma<N_CLASS><<<NBLK_E, 128, DSM2>>>(hh, hl, w2f, out);
}